// round 1
// baseline (speedup 1.0000x reference)
#include <cuda_runtime.h>
#include <cstddef>

// Problem constants
#define Bd 4
#define Sd 1024
#define Dd 1024
#define Ed 8
#define Rd 8
#define Hd 16
#define DHd 64
#define Md (Bd*Sd)            // 4096 rows (B*S)
#define OUT_OFF ((size_t)Bd*Sd*Dd) // 4194304: out first, qk second

// ---------------- scratch (static device memory; no allocations) ----------------
__device__ float g_xp[Md*Dd];        // router conv output [B,S,D]
__device__ float g_q[Md*Dd];
__device__ float g_k[Md*Dd];
__device__ float g_v[Md*Dd];
__device__ float g_wv[Md*Dd];        // attention output (pre o-proj)
__device__ float g_h[Md*64];         // LoRA intermediate [B*S, E*R]
__device__ float g_ct[3*Dd*Dd];      // conv_w transposed: [t][o][i]
__device__ float g_Bt[Dd*64];        // LoRA B transposed: [n][e*8+r]
__device__ float g_scores[Md];
__device__ float g_wsm[Md];
__device__ float g_pooled[Bd*Dd];
__device__ float g_route[Bd*Ed];
__device__ float g_rowmax[Bd*Hd*Sd];
__device__ float g_rowsum[Bd*Hd*Sd];

// ---------------- helpers ----------------
__device__ __forceinline__ float warpRedSum(float v){
    #pragma unroll
    for (int o=16;o;o>>=1) v += __shfl_xor_sync(0xffffffffu, v, o);
    return v;
}
__device__ __forceinline__ float warpRedMax(float v){
    #pragma unroll
    for (int o=16;o;o>>=1) v = fmaxf(v, __shfl_xor_sync(0xffffffffu, v, o));
    return v;
}

// Fast e^x for x <= 0 (softmax after max-subtraction). FMA-only (no MUFU).
// 2^t = 2^floor(t) * poly(frac), degree-6 Taylor of 2^f, rel err ~2e-5.
__device__ __forceinline__ float fexp(float x){
    float t = x * 1.4426950408889634f;
    t = fmaxf(t, -126.0f);
    float ti = floorf(t);
    float f = t - ti;
    float p = 1.5403530393381608e-4f;
    p = fmaf(p, f, 1.3333558146428443e-3f);
    p = fmaf(p, f, 9.6181291076284770e-3f);
    p = fmaf(p, f, 5.5504108664821580e-2f);
    p = fmaf(p, f, 2.4022650695910070e-1f);
    p = fmaf(p, f, 6.9314718055994530e-1f);
    p = fmaf(p, f, 1.0f);
    float sc = __int_as_float(((int)ti + 127) << 23);
    return sc * p;
}

// ---------------- transposes ----------------
__global__ void tr_convw(const float* __restrict__ cw, float* __restrict__ ct){
    size_t idx = (size_t)blockIdx.x*blockDim.x + threadIdx.x;
    if (idx >= (size_t)3*Dd*Dd) return;
    int t = (int)(idx / ((size_t)Dd*Dd));
    int rem = (int)(idx - (size_t)t*Dd*Dd);
    int o = rem >> 10, i = rem & 1023;
    ct[idx] = cw[(size_t)o*Dd*3 + (size_t)i*3 + t];
}

__global__ void tr_loraB(const float* __restrict__ Bp, float* __restrict__ Bt){
    int idx = blockIdx.x*blockDim.x + threadIdx.x; // 65536
    if (idx >= Dd*64) return;
    int n = idx >> 6, e = (idx >> 3) & 7, r = idx & 7;
    Bt[idx] = Bp[(size_t)e*Dd*Rd + (size_t)n*Rd + r];
}

// ---------------- generic NT SGEMM: C = alpha * A(MxK) * B(NxK)^T ----------------
// epilogue: optional route scale (for LoRA h), bias, accumulate.
__global__ __launch_bounds__(256) void sgemm_nt(
    const float* __restrict__ A, const float* __restrict__ B, float* __restrict__ C,
    int M, int N, int K, int lda, int ldb, int ldc,
    long long sAb, long long sAh, long long sBb, long long sBh,
    long long sCb, long long sCh, int ZH,
    float alpha, const float* __restrict__ bias, const float* __restrict__ route, int addC)
{
    int z = blockIdx.z;
    int zb = z / ZH, zh = z - zb*ZH;
    A += (size_t)zb*sAb + (size_t)zh*sAh;
    B += (size_t)zb*sBb + (size_t)zh*sBh;
    C += (size_t)zb*sCb + (size_t)zh*sCh;

    __shared__ __align__(16) float As[8][128];
    __shared__ __align__(16) float Bs[8][128];
    const int tid = threadIdx.x;
    const int bm = blockIdx.y*128, bn = blockIdx.x*128;
    const int tx = tid & 15, ty = tid >> 4;
    const int lm = tid >> 1;
    const int lk = (tid & 1) * 4;

    float acc[8][8];
    #pragma unroll
    for (int i=0;i<8;i++)
        #pragma unroll
        for (int j=0;j<8;j++) acc[i][j] = 0.f;

    const bool aok = (bm+lm) < M;
    const bool bok = (bn+lm) < N;
    const float* Aptr = A + (size_t)(aok ? (bm+lm) : 0)*lda + lk;
    const float* Bptr = B + (size_t)(bok ? (bn+lm) : 0)*ldb + lk;

    for (int k0 = 0; k0 < K; k0 += 8) {
        float4 av = make_float4(0.f,0.f,0.f,0.f);
        float4 bv = make_float4(0.f,0.f,0.f,0.f);
        if (aok) av = *(const float4*)(Aptr + k0);
        if (bok) bv = *(const float4*)(Bptr + k0);
        As[lk+0][lm]=av.x; As[lk+1][lm]=av.y; As[lk+2][lm]=av.z; As[lk+3][lm]=av.w;
        Bs[lk+0][lm]=bv.x; Bs[lk+1][lm]=bv.y; Bs[lk+2][lm]=bv.z; Bs[lk+3][lm]=bv.w;
        __syncthreads();
        #pragma unroll
        for (int kk=0; kk<8; kk++){
            float a[8], b[8];
            *(float4*)&a[0] = *(const float4*)&As[kk][ty*8];
            *(float4*)&a[4] = *(const float4*)&As[kk][ty*8+4];
            *(float4*)&b[0] = *(const float4*)&Bs[kk][tx*8];
            *(float4*)&b[4] = *(const float4*)&Bs[kk][tx*8+4];
            #pragma unroll
            for (int i=0;i<8;i++)
                #pragma unroll
                for (int j=0;j<8;j++)
                    acc[i][j] = fmaf(a[i], b[j], acc[i][j]);
        }
        __syncthreads();
    }

    #pragma unroll
    for (int i=0;i<8;i++){
        int m = bm + ty*8 + i;
        if (m >= M) continue;
        #pragma unroll
        for (int j=0;j<8;j++){
            int n = bn + tx*8 + j;
            if (n >= N) continue;
            float val = alpha * acc[i][j];
            if (route) val *= route[((m>>10)<<3) + (n>>3)];
            if (bias)  val += bias[n];
            float* cp = C + (size_t)m*ldc + n;
            if (addC) val += *cp;
            *cp = val;
        }
    }
}

// ---------------- conv1d (k=3, pad=1) as GEMM: xp[b,s,o] ----------------
__global__ __launch_bounds__(256) void conv_gemm(
    const float* __restrict__ x, const float* __restrict__ ct,
    const float* __restrict__ cb, float* __restrict__ xp)
{
    const int tid = threadIdx.x;
    const int bm = blockIdx.y*128, bn = blockIdx.x*128;
    const int tx = tid & 15, ty = tid >> 4;
    const int lm = tid >> 1, lk = (tid & 1)*4;
    const int mrow = bm + lm;
    const int b = mrow >> 10, s = mrow & 1023;

    __shared__ __align__(16) float As[8][128];
    __shared__ __align__(16) float Bs[8][128];
    float acc[8][8];
    #pragma unroll
    for (int i=0;i<8;i++)
        #pragma unroll
        for (int j=0;j<8;j++) acc[i][j]=0.f;

    for (int t=0;t<3;t++){
        int s2 = s + t - 1;
        bool ok = ((unsigned)s2 < 1024u);
        const float* Arow = x + ((size_t)b*Sd + (ok ? s2 : 0))*Dd + lk;
        const float* Brow = ct + (size_t)t*Dd*Dd + (size_t)(bn+lm)*Dd + lk;
        for (int k0=0;k0<Dd;k0+=8){
            float4 av = make_float4(0.f,0.f,0.f,0.f);
            if (ok) av = *(const float4*)(Arow + k0);
            float4 bv = *(const float4*)(Brow + k0);
            As[lk+0][lm]=av.x; As[lk+1][lm]=av.y; As[lk+2][lm]=av.z; As[lk+3][lm]=av.w;
            Bs[lk+0][lm]=bv.x; Bs[lk+1][lm]=bv.y; Bs[lk+2][lm]=bv.z; Bs[lk+3][lm]=bv.w;
            __syncthreads();
            #pragma unroll
            for (int kk=0; kk<8; kk++){
                float a[8], b2[8];
                *(float4*)&a[0]  = *(const float4*)&As[kk][ty*8];
                *(float4*)&a[4]  = *(const float4*)&As[kk][ty*8+4];
                *(float4*)&b2[0] = *(const float4*)&Bs[kk][tx*8];
                *(float4*)&b2[4] = *(const float4*)&Bs[kk][tx*8+4];
                #pragma unroll
                for (int i=0;i<8;i++)
                    #pragma unroll
                    for (int j=0;j<8;j++)
                        acc[i][j] = fmaf(a[i], b2[j], acc[i][j]);
            }
            __syncthreads();
        }
    }
    #pragma unroll
    for (int i=0;i<8;i++){
        int m = bm + ty*8 + i;
        #pragma unroll
        for (int j=0;j<8;j++){
            int n = bn + tx*8 + j;
            xp[(size_t)m*Dd + n] = acc[i][j] + cb[n];
        }
    }
}

// ---------------- router small kernels ----------------
__global__ void scores_k(const float* __restrict__ xp, const float* __restrict__ pw,
                         const float* __restrict__ pb, float* __restrict__ scores){
    int row = blockIdx.x;               // 4096
    int tid = threadIdx.x;              // 128
    const float4* xr = (const float4*)(xp + (size_t)row*Dd);
    const float4* pr = (const float4*)pw;
    float s = 0.f;
    #pragma unroll
    for (int i=0;i<2;i++){
        float4 a = xr[tid*2+i], b = pr[tid*2+i];
        s += a.x*b.x + a.y*b.y + a.z*b.z + a.w*b.w;
    }
    s = warpRedSum(s);
    __shared__ float sm[4];
    if ((tid&31)==0) sm[tid>>5]=s;
    __syncthreads();
    if (tid==0) scores[row] = sm[0]+sm[1]+sm[2]+sm[3] + pb[0];
}

__global__ void softmax_w(const float* __restrict__ scores, float* __restrict__ w){
    int b = blockIdx.x; int tid = threadIdx.x; // 256
    float4 v = *(const float4*)(scores + (size_t)b*Sd + tid*4);
    float m = fmaxf(fmaxf(v.x,v.y), fmaxf(v.z,v.w));
    m = warpRedMax(m);
    __shared__ float sm[8];
    __shared__ float gmax, gisum;
    if ((tid&31)==0) sm[tid>>5]=m;
    __syncthreads();
    if (tid==0){ float mm=sm[0]; for(int i=1;i<8;i++) mm=fmaxf(mm,sm[i]); gmax=mm; }
    __syncthreads();
    float e0=expf(v.x-gmax), e1=expf(v.y-gmax), e2=expf(v.z-gmax), e3=expf(v.w-gmax);
    float s = e0+e1+e2+e3;
    s = warpRedSum(s);
    if ((tid&31)==0) sm[tid>>5]=s;
    __syncthreads();
    if (tid==0){ float ss=0; for(int i=0;i<8;i++) ss+=sm[i]; gisum = 1.f/ss; }
    __syncthreads();
    float4 o = make_float4(e0*gisum, e1*gisum, e2*gisum, e3*gisum);
    *(float4*)(w + (size_t)b*Sd + tid*4) = o;
}

__global__ void pooled_k(const float* __restrict__ xp, const float* __restrict__ w,
                         float* __restrict__ pooled){
    int b = blockIdx.y;
    int d = blockIdx.x*128 + threadIdx.x;
    __shared__ float ws[Sd];
    for (int i = threadIdx.x; i < Sd; i += 128) ws[i] = w[(size_t)b*Sd + i];
    __syncthreads();
    float s = 0.f;
    const float* base = xp + (size_t)b*Sd*Dd + d;
    for (int i=0;i<Sd;i++) s = fmaf(ws[i], base[(size_t)i*Dd], s);
    pooled[b*Dd + d] = s;
}

__global__ void route_k(const float* __restrict__ pooled, const float* __restrict__ rw,
                        const float* __restrict__ rb, float* __restrict__ route){
    int tid = threadIdx.x; // 256
    int e = tid >> 5, lane = tid & 31;
    __shared__ float lg[8];
    for (int b=0;b<Bd;b++){
        float s=0.f;
        for (int d=lane; d<Dd; d+=32) s += pooled[b*Dd+d]*rw[e*Dd+d];
        s = warpRedSum(s);
        if (lane==0) lg[e] = s + rb[e];
        __syncthreads();
        if (tid==0){
            float mm=lg[0];
            for (int i=1;i<8;i++) mm=fmaxf(mm,lg[i]);
            float ex[8]; float ss=0.f;
            for (int i=0;i<8;i++){ ex[i]=expf(lg[i]-mm); ss+=ex[i]; }
            float inv = 1.f/ss;
            for (int i=0;i<8;i++) route[b*8+i]=ex[i]*inv;
        }
        __syncthreads();
    }
}

// ---------------- attention ----------------
__global__ void row_max_k(const float* __restrict__ qk, float* __restrict__ rowmax){
    int row = blockIdx.x;               // 65536
    int tid = threadIdx.x;              // 128
    const float4* p = (const float4*)(qk + (size_t)row*Sd);
    float4 a = p[tid*2], b = p[tid*2+1];
    float m = fmaxf(fmaxf(fmaxf(a.x,a.y),fmaxf(a.z,a.w)),
                    fmaxf(fmaxf(b.x,b.y),fmaxf(b.z,b.w)));
    m = warpRedMax(m);
    __shared__ float sm[4];
    if ((tid&31)==0) sm[tid>>5]=m;
    __syncthreads();
    if (tid==0) rowmax[row] = fmaxf(fmaxf(sm[0],sm[1]), fmaxf(sm[2],sm[3]));
}

// PV: wv_un[b,i,h*64+d] = sum_j exp(qk - rowmax) * v ; also emits row sums.
// grid (1, S/128, B*H), block 256. N-tile = 64 (= dh).
__global__ __launch_bounds__(256) void attn_pv(
    const float* __restrict__ qk, const float* __restrict__ v,
    const float* __restrict__ rowmax, float* __restrict__ wv, float* __restrict__ rowsum)
{
    const int z = blockIdx.z;
    const int bq = z >> 4, h = z & 15;
    const float* Aq = qk + (size_t)z * Sd * Sd;
    const float* Vh = v + (size_t)bq * Sd * Dd + h*DHd;
    float* Cw = wv + (size_t)bq * Sd * Dd + h*DHd;
    const float* rmax = rowmax + (size_t)z*Sd;
    const int bm = blockIdx.y * 128;

    __shared__ __align__(16) float Ps[16][128];
    __shared__ __align__(16) float Vs[16][64];
    __shared__ float Sred[128][4];

    const int tid = threadIdx.x;
    const int tx = tid & 15, ty = tid >> 4;
    const int m0 = tid >> 2;            // 0..63
    const int kq = (tid & 3) * 4;
    const int kv = tid >> 4;            // 0..15
    const int dq = (tid & 15) * 4;

    const float rm0 = rmax[bm + m0];
    const float rm1 = rmax[bm + m0 + 64];

    float acc[8][4];
    #pragma unroll
    for (int i=0;i<8;i++)
        #pragma unroll
        for (int j=0;j<4;j++) acc[i][j]=0.f;
    float ps0 = 0.f, ps1 = 0.f;

    const float* Ar0 = Aq + (size_t)(bm+m0)*Sd + kq;
    const float* Ar1 = Ar0 + (size_t)64*Sd;

    for (int k0=0; k0<Sd; k0+=16){
        float4 a0 = *(const float4*)(Ar0 + k0);
        float4 a1 = *(const float4*)(Ar1 + k0);
        float p00=fexp(a0.x-rm0), p01=fexp(a0.y-rm0), p02=fexp(a0.z-rm0), p03=fexp(a0.w-rm0);
        float p10=fexp(a1.x-rm1), p11=fexp(a1.y-rm1), p12=fexp(a1.z-rm1), p13=fexp(a1.w-rm1);
        Ps[kq+0][m0]=p00; Ps[kq+1][m0]=p01; Ps[kq+2][m0]=p02; Ps[kq+3][m0]=p03;
        Ps[kq+0][m0+64]=p10; Ps[kq+1][m0+64]=p11; Ps[kq+2][m0+64]=p12; Ps[kq+3][m0+64]=p13;
        ps0 += p00+p01+p02+p03;
        ps1 += p10+p11+p12+p13;
        float4 vv = *(const float4*)(Vh + (size_t)(k0+kv)*Dd + dq);
        *(float4*)&Vs[kv][dq] = vv;
        __syncthreads();
        #pragma unroll
        for (int kk=0; kk<16; kk++){
            float a[8], bb[4];
            *(float4*)&a[0] = *(const float4*)&Ps[kk][ty*8];
            *(float4*)&a[4] = *(const float4*)&Ps[kk][ty*8+4];
            *(float4*)&bb[0] = *(const float4*)&Vs[kk][tx*4];
            #pragma unroll
            for (int i=0;i<8;i++)
                #pragma unroll
                for (int j=0;j<4;j++)
                    acc[i][j] = fmaf(a[i], bb[j], acc[i][j]);
        }
        __syncthreads();
    }

    Sred[m0][tid&3] = ps0;
    Sred[m0+64][tid&3] = ps1;
    __syncthreads();
    if (tid < 128)
        rowsum[(size_t)z*Sd + bm + tid] = Sred[tid][0]+Sred[tid][1]+Sred[tid][2]+Sred[tid][3];

    #pragma unroll
    for (int i=0;i<8;i++){
        size_t rowoff = (size_t)(bm + ty*8 + i)*Dd;
        #pragma unroll
        for (int j=0;j<4;j++)
            Cw[rowoff + tx*4 + j] = acc[i][j];
    }
}

__global__ void norm_wv(float* __restrict__ wv, const float* __restrict__ rowsum){
    int m = blockIdx.x;                 // 4096 = b*S + i
    int b = m >> 10, i = m & 1023;
    int tid = threadIdx.x;              // 256
    __shared__ float inv[16];
    if (tid < 16) inv[tid] = 1.f / rowsum[((size_t)(b*Hd + tid))*Sd + i];
    __syncthreads();
    float4* p = (float4*)(wv + (size_t)m*Dd);
    float4 vv = p[tid];
    float sc = inv[(tid*4) >> 6];
    vv.x*=sc; vv.y*=sc; vv.z*=sc; vv.w*=sc;
    p[tid]=vv;
}

// ---------------- host launcher ----------------
extern "C" void kernel_launch(void* const* d_in, const int* in_sizes, int n_in,
                              void* d_out, int out_size)
{
    (void)in_sizes; (void)n_in; (void)out_size;
    const float* x      = (const float*)d_in[0];
    const float* conv_w = (const float*)d_in[1];
    const float* conv_b = (const float*)d_in[2];
    const float* pool_w = (const float*)d_in[3];
    const float* pool_b = (const float*)d_in[4];
    const float* rlin_w = (const float*)d_in[5];
    const float* rlin_b = (const float*)d_in[6];
    const float* qW=(const float*)d_in[7],  *qb=(const float*)d_in[8];
    const float* qA=(const float*)d_in[9],  *qB=(const float*)d_in[10];
    const float* kW=(const float*)d_in[11], *kA=(const float*)d_in[12], *kB=(const float*)d_in[13];
    const float* vW=(const float*)d_in[14], *vb=(const float*)d_in[15];
    const float* vA=(const float*)d_in[16], *vB=(const float*)d_in[17];
    const float* oW=(const float*)d_in[18], *ob=(const float*)d_in[19];
    const float* oA=(const float*)d_in[20], *oB=(const float*)d_in[21];

    float* out = (float*)d_out;
    float* qk  = out + OUT_OFF;

    float *xp,*q,*k,*v,*wv,*h,*ct,*Bt,*scores,*w,*pooled,*route,*rowmax,*rowsum;
    cudaGetSymbolAddress((void**)&xp, g_xp);
    cudaGetSymbolAddress((void**)&q,  g_q);
    cudaGetSymbolAddress((void**)&k,  g_k);
    cudaGetSymbolAddress((void**)&v,  g_v);
    cudaGetSymbolAddress((void**)&wv, g_wv);
    cudaGetSymbolAddress((void**)&h,  g_h);
    cudaGetSymbolAddress((void**)&ct, g_ct);
    cudaGetSymbolAddress((void**)&Bt, g_Bt);
    cudaGetSymbolAddress((void**)&scores, g_scores);
    cudaGetSymbolAddress((void**)&w,  g_wsm);
    cudaGetSymbolAddress((void**)&pooled, g_pooled);
    cudaGetSymbolAddress((void**)&route,  g_route);
    cudaGetSymbolAddress((void**)&rowmax, g_rowmax);
    cudaGetSymbolAddress((void**)&rowsum, g_rowsum);

    const long long SD = (long long)Sd*Dd;
    const long long SS = (long long)Sd*Sd;

    // --- router ---
    tr_convw<<<(3*Dd*Dd + 255)/256, 256>>>(conv_w, ct);
    conv_gemm<<<dim3(8,32,1), 256>>>(x, ct, conv_b, xp);
    scores_k<<<Md, 128>>>(xp, pool_w, pool_b, scores);
    softmax_w<<<Bd, 256>>>(scores, w);
    pooled_k<<<dim3(8,Bd), 128>>>(xp, w, pooled);
    route_k<<<1, 256>>>(pooled, rlin_w, rlin_b, route);

    // --- q/k/v projections: base + LoRA ---
    const float* Ws[3]  = {qW, kW, vW};
    const float* bs[3]  = {qb, nullptr, vb};
    const float* As_[3] = {qA, kA, vA};
    const float* Bs_[3] = {qB, kB, vB};
    float* outs[3] = {q, k, v};
    for (int p = 0; p < 3; p++){
        sgemm_nt<<<dim3(8,32,1),256>>>(x, Ws[p], outs[p], Md, Dd, Dd, Dd, Dd, Dd,
                                       0,0,0,0,0,0,1, 1.f, bs[p], nullptr, 0);
        tr_loraB<<<(Dd*64+255)/256, 256>>>(Bs_[p], Bt);
        sgemm_nt<<<dim3(1,32,1),256>>>(x, As_[p], h, Md, 64, Dd, Dd, Dd, 64,
                                       0,0,0,0,0,0,1, 1.f, nullptr, route, 0);
        sgemm_nt<<<dim3(8,32,1),256>>>(h, Bt, outs[p], Md, Dd, 64, 64, 64, Dd,
                                       0,0,0,0,0,0,1, 2.0f, nullptr, nullptr, 1);
    }

    // --- qk logits (written straight into d_out), scale = dh^-0.5 = 0.125 ---
    sgemm_nt<<<dim3(8,8,Bd*Hd),256>>>(q, k, qk, Sd, Sd, DHd, Dd, Dd, Sd,
                                      SD, 64, SD, 64, (long long)Hd*SS, SS, Hd,
                                      0.125f, nullptr, nullptr, 0);

    // --- softmax + PV ---
    row_max_k<<<Bd*Hd*Sd, 128>>>(qk, rowmax);
    attn_pv<<<dim3(1, Sd/128, Bd*Hd), 256>>>(qk, v, rowmax, wv, rowsum);
    norm_wv<<<Md, 256>>>(wv, rowsum);

    // --- o projection: base + LoRA, into d_out[0 : B*S*D] ---
    sgemm_nt<<<dim3(8,32,1),256>>>(wv, oW, out, Md, Dd, Dd, Dd, Dd, Dd,
                                   0,0,0,0,0,0,1, 1.f, ob, nullptr, 0);
    tr_loraB<<<(Dd*64+255)/256, 256>>>(oB, Bt);
    sgemm_nt<<<dim3(1,32,1),256>>>(wv, oA, h, Md, 64, Dd, Dd, Dd, 64,
                                   0,0,0,0,0,0,1, 1.f, nullptr, route, 0);
    sgemm_nt<<<dim3(8,32,1),256>>>(h, Bt, out, Md, Dd, 64, 64, 64, Dd,
                                   0,0,0,0,0,0,1, 2.0f, nullptr, nullptr, 1);
}

// round 2
// speedup vs baseline: 1.0028x; 1.0028x over previous
#include <cuda_runtime.h>
#include <cstddef>

// Problem constants
#define Bd 4
#define Sd 1024
#define Dd 1024
#define Ed 8
#define Rd 8
#define Hd 16
#define DHd 64
#define Md (Bd*Sd)            // 4096 rows (B*S)
#define OUT_OFF ((size_t)Bd*Sd*Dd) // 4194304: out first, qk second

// ---------------- scratch (static device memory; no allocations) ----------------
__device__ float g_xp[Md*Dd];        // router conv output [B,S,D]
__device__ float g_q[Md*Dd];
__device__ float g_k[Md*Dd];
__device__ float g_v[Md*Dd];
__device__ float g_wv[Md*Dd];        // attention output (pre o-proj)
__device__ float g_h[Md*64];         // LoRA intermediate [B*S, E*R]
__device__ float g_ct[3*Dd*Dd];      // conv_w transposed: [t][o][i]
__device__ float g_Bt[Dd*64];        // LoRA B transposed: [n][e*8+r]
__device__ float g_scores[Md];
__device__ float g_wsm[Md];
__device__ float g_pooled[Bd*Dd];
__device__ float g_route[Bd*Ed];
__device__ float g_rowmax[Bd*Hd*Sd];
__device__ float g_rowsum[Bd*Hd*Sd];

// ---------------- helpers ----------------
__device__ __forceinline__ float warpRedSum(float v){
    #pragma unroll
    for (int o=16;o;o>>=1) v += __shfl_xor_sync(0xffffffffu, v, o);
    return v;
}
__device__ __forceinline__ float warpRedMax(float v){
    #pragma unroll
    for (int o=16;o;o>>=1) v = fmaxf(v, __shfl_xor_sync(0xffffffffu, v, o));
    return v;
}

// Fast e^x for x <= 0 (softmax after max-subtraction). FMA-only (no MUFU).
// 2^t = 2^floor(t) * poly(frac), degree-6 Taylor of 2^f, rel err ~2e-5.
__device__ __forceinline__ float fexp(float x){
    float t = x * 1.4426950408889634f;
    t = fmaxf(t, -126.0f);
    float ti = floorf(t);
    float f = t - ti;
    float p = 1.5403530393381608e-4f;
    p = fmaf(p, f, 1.3333558146428443e-3f);
    p = fmaf(p, f, 9.6181291076284770e-3f);
    p = fmaf(p, f, 5.5504108664821580e-2f);
    p = fmaf(p, f, 2.4022650695910070e-1f);
    p = fmaf(p, f, 6.9314718055994530e-1f);
    p = fmaf(p, f, 1.0f);
    float sc = __int_as_float(((int)ti + 127) << 23);
    return sc * p;
}

// ---------------- transposes ----------------
__global__ void tr_convw(const float* __restrict__ cw, float* __restrict__ ct){
    size_t idx = (size_t)blockIdx.x*blockDim.x + threadIdx.x;
    if (idx >= (size_t)3*Dd*Dd) return;
    int t = (int)(idx / ((size_t)Dd*Dd));
    int rem = (int)(idx - (size_t)t*Dd*Dd);
    int o = rem >> 10, i = rem & 1023;
    ct[idx] = cw[(size_t)o*Dd*3 + (size_t)i*3 + t];
}

__global__ void tr_loraB(const float* __restrict__ Bp, float* __restrict__ Bt){
    int idx = blockIdx.x*blockDim.x + threadIdx.x; // 65536
    if (idx >= Dd*64) return;
    int n = idx >> 6, e = (idx >> 3) & 7, r = idx & 7;
    Bt[idx] = Bp[(size_t)e*Dd*Rd + (size_t)n*Rd + r];
}

// ---------------- generic NT SGEMM: C = alpha * A(MxK) * B(NxK)^T ----------------
// epilogue: optional route scale (for LoRA h), bias, accumulate.
__global__ __launch_bounds__(256) void sgemm_nt(
    const float* __restrict__ A, const float* __restrict__ B, float* __restrict__ C,
    int M, int N, int K, int lda, int ldb, int ldc,
    long long sAb, long long sAh, long long sBb, long long sBh,
    long long sCb, long long sCh, int ZH,
    float alpha, const float* __restrict__ bias, const float* __restrict__ route, int addC)
{
    int z = blockIdx.z;
    int zb = z / ZH, zh = z - zb*ZH;
    A += (size_t)zb*sAb + (size_t)zh*sAh;
    B += (size_t)zb*sBb + (size_t)zh*sBh;
    C += (size_t)zb*sCb + (size_t)zh*sCh;

    __shared__ __align__(16) float As[8][128];
    __shared__ __align__(16) float Bs[8][128];
    const int tid = threadIdx.x;
    const int bm = blockIdx.y*128, bn = blockIdx.x*128;
    const int tx = tid & 15, ty = tid >> 4;
    const int lm = tid >> 1;
    const int lk = (tid & 1) * 4;

    float acc[8][8];
    #pragma unroll
    for (int i=0;i<8;i++)
        #pragma unroll
        for (int j=0;j<8;j++) acc[i][j] = 0.f;

    const bool aok = (bm+lm) < M;
    const bool bok = (bn+lm) < N;
    const float* Aptr = A + (size_t)(aok ? (bm+lm) : 0)*lda + lk;
    const float* Bptr = B + (size_t)(bok ? (bn+lm) : 0)*ldb + lk;

    for (int k0 = 0; k0 < K; k0 += 8) {
        float4 av = make_float4(0.f,0.f,0.f,0.f);
        float4 bv = make_float4(0.f,0.f,0.f,0.f);
        if (aok) av = *(const float4*)(Aptr + k0);
        if (bok) bv = *(const float4*)(Bptr + k0);
        As[lk+0][lm]=av.x; As[lk+1][lm]=av.y; As[lk+2][lm]=av.z; As[lk+3][lm]=av.w;
        Bs[lk+0][lm]=bv.x; Bs[lk+1][lm]=bv.y; Bs[lk+2][lm]=bv.z; Bs[lk+3][lm]=bv.w;
        __syncthreads();
        #pragma unroll
        for (int kk=0; kk<8; kk++){
            float a[8], b[8];
            *(float4*)&a[0] = *(const float4*)&As[kk][ty*8];
            *(float4*)&a[4] = *(const float4*)&As[kk][ty*8+4];
            *(float4*)&b[0] = *(const float4*)&Bs[kk][tx*8];
            *(float4*)&b[4] = *(const float4*)&Bs[kk][tx*8+4];
            #pragma unroll
            for (int i=0;i<8;i++)
                #pragma unroll
                for (int j=0;j<8;j++)
                    acc[i][j] = fmaf(a[i], b[j], acc[i][j]);
        }
        __syncthreads();
    }

    #pragma unroll
    for (int i=0;i<8;i++){
        int m = bm + ty*8 + i;
        if (m >= M) continue;
        #pragma unroll
        for (int j=0;j<8;j++){
            int n = bn + tx*8 + j;
            if (n >= N) continue;
            float val = alpha * acc[i][j];
            if (route) val *= route[((m>>10)<<3) + (n>>3)];
            if (bias)  val += bias[n];
            float* cp = C + (size_t)m*ldc + n;
            if (addC) val += *cp;
            *cp = val;
        }
    }
}

// ---------------- conv1d (k=3, pad=1) as GEMM: xp[b,s,o] ----------------
__global__ __launch_bounds__(256) void conv_gemm(
    const float* __restrict__ x, const float* __restrict__ ct,
    const float* __restrict__ cb, float* __restrict__ xp)
{
    const int tid = threadIdx.x;
    const int bm = blockIdx.y*128, bn = blockIdx.x*128;
    const int tx = tid & 15, ty = tid >> 4;
    const int lm = tid >> 1, lk = (tid & 1)*4;
    const int mrow = bm + lm;
    const int b = mrow >> 10, s = mrow & 1023;

    __shared__ __align__(16) float As[8][128];
    __shared__ __align__(16) float Bs[8][128];
    float acc[8][8];
    #pragma unroll
    for (int i=0;i<8;i++)
        #pragma unroll
        for (int j=0;j<8;j++) acc[i][j]=0.f;

    for (int t=0;t<3;t++){
        int s2 = s + t - 1;
        bool ok = ((unsigned)s2 < 1024u);
        const float* Arow = x + ((size_t)b*Sd + (ok ? s2 : 0))*Dd + lk;
        const float* Brow = ct + (size_t)t*Dd*Dd + (size_t)(bn+lm)*Dd + lk;
        for (int k0=0;k0<Dd;k0+=8){
            float4 av = make_float4(0.f,0.f,0.f,0.f);
            if (ok) av = *(const float4*)(Arow + k0);
            float4 bv = *(const float4*)(Brow + k0);
            As[lk+0][lm]=av.x; As[lk+1][lm]=av.y; As[lk+2][lm]=av.z; As[lk+3][lm]=av.w;
            Bs[lk+0][lm]=bv.x; Bs[lk+1][lm]=bv.y; Bs[lk+2][lm]=bv.z; Bs[lk+3][lm]=bv.w;
            __syncthreads();
            #pragma unroll
            for (int kk=0; kk<8; kk++){
                float a[8], b2[8];
                *(float4*)&a[0]  = *(const float4*)&As[kk][ty*8];
                *(float4*)&a[4]  = *(const float4*)&As[kk][ty*8+4];
                *(float4*)&b2[0] = *(const float4*)&Bs[kk][tx*8];
                *(float4*)&b2[4] = *(const float4*)&Bs[kk][tx*8+4];
                #pragma unroll
                for (int i=0;i<8;i++)
                    #pragma unroll
                    for (int j=0;j<8;j++)
                        acc[i][j] = fmaf(a[i], b2[j], acc[i][j]);
            }
            __syncthreads();
        }
    }
    #pragma unroll
    for (int i=0;i<8;i++){
        int m = bm + ty*8 + i;
        #pragma unroll
        for (int j=0;j<8;j++){
            int n = bn + tx*8 + j;
            xp[(size_t)m*Dd + n] = acc[i][j] + cb[n];
        }
    }
}

// ---------------- router small kernels ----------------
__global__ void scores_k(const float* __restrict__ xp, const float* __restrict__ pw,
                         const float* __restrict__ pb, float* __restrict__ scores){
    int row = blockIdx.x;               // 4096
    int tid = threadIdx.x;              // 128
    const float4* xr = (const float4*)(xp + (size_t)row*Dd);
    const float4* pr = (const float4*)pw;
    float s = 0.f;
    #pragma unroll
    for (int i=0;i<2;i++){
        float4 a = xr[tid*2+i], b = pr[tid*2+i];
        s += a.x*b.x + a.y*b.y + a.z*b.z + a.w*b.w;
    }
    s = warpRedSum(s);
    __shared__ float sm[4];
    if ((tid&31)==0) sm[tid>>5]=s;
    __syncthreads();
    if (tid==0) scores[row] = sm[0]+sm[1]+sm[2]+sm[3] + pb[0];
}

__global__ void softmax_w(const float* __restrict__ scores, float* __restrict__ w){
    int b = blockIdx.x; int tid = threadIdx.x; // 256
    float4 v = *(const float4*)(scores + (size_t)b*Sd + tid*4);
    float m = fmaxf(fmaxf(v.x,v.y), fmaxf(v.z,v.w));
    m = warpRedMax(m);
    __shared__ float sm[8];
    __shared__ float gmax, gisum;
    if ((tid&31)==0) sm[tid>>5]=m;
    __syncthreads();
    if (tid==0){ float mm=sm[0]; for(int i=1;i<8;i++) mm=fmaxf(mm,sm[i]); gmax=mm; }
    __syncthreads();
    float e0=expf(v.x-gmax), e1=expf(v.y-gmax), e2=expf(v.z-gmax), e3=expf(v.w-gmax);
    float s = e0+e1+e2+e3;
    s = warpRedSum(s);
    if ((tid&31)==0) sm[tid>>5]=s;
    __syncthreads();
    if (tid==0){ float ss=0; for(int i=0;i<8;i++) ss+=sm[i]; gisum = 1.f/ss; }
    __syncthreads();
    float4 o = make_float4(e0*gisum, e1*gisum, e2*gisum, e3*gisum);
    *(float4*)(w + (size_t)b*Sd + tid*4) = o;
}

__global__ void pooled_k(const float* __restrict__ xp, const float* __restrict__ w,
                         float* __restrict__ pooled){
    int b = blockIdx.y;
    int d = blockIdx.x*128 + threadIdx.x;
    __shared__ float ws[Sd];
    for (int i = threadIdx.x; i < Sd; i += 128) ws[i] = w[(size_t)b*Sd + i];
    __syncthreads();
    float s = 0.f;
    const float* base = xp + (size_t)b*Sd*Dd + d;
    for (int i=0;i<Sd;i++) s = fmaf(ws[i], base[(size_t)i*Dd], s);
    pooled[b*Dd + d] = s;
}

__global__ void route_k(const float* __restrict__ pooled, const float* __restrict__ rw,
                        const float* __restrict__ rb, float* __restrict__ route){
    int tid = threadIdx.x; // 256
    int e = tid >> 5, lane = tid & 31;
    __shared__ float lg[8];
    for (int b=0;b<Bd;b++){
        float s=0.f;
        for (int d=lane; d<Dd; d+=32) s += pooled[b*Dd+d]*rw[e*Dd+d];
        s = warpRedSum(s);
        if (lane==0) lg[e] = s + rb[e];
        __syncthreads();
        if (tid==0){
            float mm=lg[0];
            for (int i=1;i<8;i++) mm=fmaxf(mm,lg[i]);
            float ex[8]; float ss=0.f;
            for (int i=0;i<8;i++){ ex[i]=expf(lg[i]-mm); ss+=ex[i]; }
            float inv = 1.f/ss;
            for (int i=0;i<8;i++) route[b*8+i]=ex[i]*inv;
        }
        __syncthreads();
    }
}

// ---------------- attention ----------------
__global__ void row_max_k(const float* __restrict__ qk, float* __restrict__ rowmax){
    int row = blockIdx.x;               // 65536
    int tid = threadIdx.x;              // 128
    const float4* p = (const float4*)(qk + (size_t)row*Sd);
    float4 a = p[tid*2], b = p[tid*2+1];
    float m = fmaxf(fmaxf(fmaxf(a.x,a.y),fmaxf(a.z,a.w)),
                    fmaxf(fmaxf(b.x,b.y),fmaxf(b.z,b.w)));
    m = warpRedMax(m);
    __shared__ float sm[4];
    if ((tid&31)==0) sm[tid>>5]=m;
    __syncthreads();
    if (tid==0) rowmax[row] = fmaxf(fmaxf(sm[0],sm[1]), fmaxf(sm[2],sm[3]));
}

// PV: wv_un[b,i,h*64+d] = sum_j exp(qk - rowmax) * v ; also emits row sums.
// grid (1, S/128, B*H), block 256. N-tile = 64 (= dh).
__global__ __launch_bounds__(256) void attn_pv(
    const float* __restrict__ qk, const float* __restrict__ v,
    const float* __restrict__ rowmax, float* __restrict__ wv, float* __restrict__ rowsum)
{
    const int z = blockIdx.z;
    const int bq = z >> 4, h = z & 15;
    const float* Aq = qk + (size_t)z * Sd * Sd;
    const float* Vh = v + (size_t)bq * Sd * Dd + h*DHd;
    float* Cw = wv + (size_t)bq * Sd * Dd + h*DHd;
    const float* rmax = rowmax + (size_t)z*Sd;
    const int bm = blockIdx.y * 128;

    __shared__ __align__(16) float Ps[16][128];
    __shared__ __align__(16) float Vs[16][64];
    __shared__ float Sred[128][4];

    const int tid = threadIdx.x;
    const int tx = tid & 15, ty = tid >> 4;
    const int m0 = tid >> 2;            // 0..63
    const int kq = (tid & 3) * 4;
    const int kv = tid >> 4;            // 0..15
    const int dq = (tid & 15) * 4;

    const float rm0 = rmax[bm + m0];
    const float rm1 = rmax[bm + m0 + 64];

    float acc[8][4];
    #pragma unroll
    for (int i=0;i<8;i++)
        #pragma unroll
        for (int j=0;j<4;j++) acc[i][j]=0.f;
    float ps0 = 0.f, ps1 = 0.f;

    const float* Ar0 = Aq + (size_t)(bm+m0)*Sd + kq;
    const float* Ar1 = Ar0 + (size_t)64*Sd;

    for (int k0=0; k0<Sd; k0+=16){
        float4 a0 = *(const float4*)(Ar0 + k0);
        float4 a1 = *(const float4*)(Ar1 + k0);
        float p00=fexp(a0.x-rm0), p01=fexp(a0.y-rm0), p02=fexp(a0.z-rm0), p03=fexp(a0.w-rm0);
        float p10=fexp(a1.x-rm1), p11=fexp(a1.y-rm1), p12=fexp(a1.z-rm1), p13=fexp(a1.w-rm1);
        Ps[kq+0][m0]=p00; Ps[kq+1][m0]=p01; Ps[kq+2][m0]=p02; Ps[kq+3][m0]=p03;
        Ps[kq+0][m0+64]=p10; Ps[kq+1][m0+64]=p11; Ps[kq+2][m0+64]=p12; Ps[kq+3][m0+64]=p13;
        ps0 += p00+p01+p02+p03;
        ps1 += p10+p11+p12+p13;
        float4 vv = *(const float4*)(Vh + (size_t)(k0+kv)*Dd + dq);
        *(float4*)&Vs[kv][dq] = vv;
        __syncthreads();
        #pragma unroll
        for (int kk=0; kk<16; kk++){
            float a[8], bb[4];
            *(float4*)&a[0] = *(const float4*)&Ps[kk][ty*8];
            *(float4*)&a[4] = *(const float4*)&Ps[kk][ty*8+4];
            *(float4*)&bb[0] = *(const float4*)&Vs[kk][tx*4];
            #pragma unroll
            for (int i=0;i<8;i++)
                #pragma unroll
                for (int j=0;j<4;j++)
                    acc[i][j] = fmaf(a[i], bb[j], acc[i][j]);
        }
        __syncthreads();
    }

    Sred[m0][tid&3] = ps0;
    Sred[m0+64][tid&3] = ps1;
    __syncthreads();
    if (tid < 128)
        rowsum[(size_t)z*Sd + bm + tid] = Sred[tid][0]+Sred[tid][1]+Sred[tid][2]+Sred[tid][3];

    #pragma unroll
    for (int i=0;i<8;i++){
        size_t rowoff = (size_t)(bm + ty*8 + i)*Dd;
        #pragma unroll
        for (int j=0;j<4;j++)
            Cw[rowoff + tx*4 + j] = acc[i][j];
    }
}

__global__ void norm_wv(float* __restrict__ wv, const float* __restrict__ rowsum){
    int m = blockIdx.x;                 // 4096 = b*S + i
    int b = m >> 10, i = m & 1023;
    int tid = threadIdx.x;              // 256
    __shared__ float inv[16];
    if (tid < 16) inv[tid] = 1.f / rowsum[((size_t)(b*Hd + tid))*Sd + i];
    __syncthreads();
    float4* p = (float4*)(wv + (size_t)m*Dd);
    float4 vv = p[tid];
    float sc = inv[(tid*4) >> 6];
    vv.x*=sc; vv.y*=sc; vv.z*=sc; vv.w*=sc;
    p[tid]=vv;
}

// ---------------- host launcher ----------------
extern "C" void kernel_launch(void* const* d_in, const int* in_sizes, int n_in,
                              void* d_out, int out_size)
{
    (void)in_sizes; (void)n_in; (void)out_size;
    const float* x      = (const float*)d_in[0];
    const float* conv_w = (const float*)d_in[1];
    const float* conv_b = (const float*)d_in[2];
    const float* pool_w = (const float*)d_in[3];
    const float* pool_b = (const float*)d_in[4];
    const float* rlin_w = (const float*)d_in[5];
    const float* rlin_b = (const float*)d_in[6];
    const float* qW=(const float*)d_in[7],  *qb=(const float*)d_in[8];
    const float* qA=(const float*)d_in[9],  *qB=(const float*)d_in[10];
    const float* kW=(const float*)d_in[11], *kA=(const float*)d_in[12], *kB=(const float*)d_in[13];
    const float* vW=(const float*)d_in[14], *vb=(const float*)d_in[15];
    const float* vA=(const float*)d_in[16], *vB=(const float*)d_in[17];
    const float* oW=(const float*)d_in[18], *ob=(const float*)d_in[19];
    const float* oA=(const float*)d_in[20], *oB=(const float*)d_in[21];

    float* out = (float*)d_out;
    float* qk  = out + OUT_OFF;

    float *xp,*q,*k,*v,*wv,*h,*ct,*Bt,*scores,*w,*pooled,*route,*rowmax,*rowsum;
    cudaGetSymbolAddress((void**)&xp, g_xp);
    cudaGetSymbolAddress((void**)&q,  g_q);
    cudaGetSymbolAddress((void**)&k,  g_k);
    cudaGetSymbolAddress((void**)&v,  g_v);
    cudaGetSymbolAddress((void**)&wv, g_wv);
    cudaGetSymbolAddress((void**)&h,  g_h);
    cudaGetSymbolAddress((void**)&ct, g_ct);
    cudaGetSymbolAddress((void**)&Bt, g_Bt);
    cudaGetSymbolAddress((void**)&scores, g_scores);
    cudaGetSymbolAddress((void**)&w,  g_wsm);
    cudaGetSymbolAddress((void**)&pooled, g_pooled);
    cudaGetSymbolAddress((void**)&route,  g_route);
    cudaGetSymbolAddress((void**)&rowmax, g_rowmax);
    cudaGetSymbolAddress((void**)&rowsum, g_rowsum);

    const long long SD = (long long)Sd*Dd;
    const long long SS = (long long)Sd*Sd;

    // --- router ---
    tr_convw<<<(3*Dd*Dd + 255)/256, 256>>>(conv_w, ct);
    conv_gemm<<<dim3(8,32,1), 256>>>(x, ct, conv_b, xp);
    scores_k<<<Md, 128>>>(xp, pool_w, pool_b, scores);
    softmax_w<<<Bd, 256>>>(scores, w);
    pooled_k<<<dim3(8,Bd), 128>>>(xp, w, pooled);
    route_k<<<1, 256>>>(pooled, rlin_w, rlin_b, route);

    // --- q/k/v projections: base + LoRA ---
    const float* Ws[3]  = {qW, kW, vW};
    const float* bs[3]  = {qb, nullptr, vb};
    const float* As_[3] = {qA, kA, vA};
    const float* Bs_[3] = {qB, kB, vB};
    float* outs[3] = {q, k, v};
    for (int p = 0; p < 3; p++){
        sgemm_nt<<<dim3(8,32,1),256>>>(x, Ws[p], outs[p], Md, Dd, Dd, Dd, Dd, Dd,
                                       0,0,0,0,0,0,1, 1.f, bs[p], nullptr, 0);
        tr_loraB<<<(Dd*64+255)/256, 256>>>(Bs_[p], Bt);
        sgemm_nt<<<dim3(1,32,1),256>>>(x, As_[p], h, Md, 64, Dd, Dd, Dd, 64,
                                       0,0,0,0,0,0,1, 1.f, nullptr, route, 0);
        sgemm_nt<<<dim3(8,32,1),256>>>(h, Bt, outs[p], Md, Dd, 64, 64, 64, Dd,
                                       0,0,0,0,0,0,1, 2.0f, nullptr, nullptr, 1);
    }

    // --- qk logits (written straight into d_out), scale = dh^-0.5 = 0.125 ---
    sgemm_nt<<<dim3(8,8,Bd*Hd),256>>>(q, k, qk, Sd, Sd, DHd, Dd, Dd, Sd,
                                      SD, 64, SD, 64, (long long)Hd*SS, SS, Hd,
                                      0.125f, nullptr, nullptr, 0);

    // --- softmax + PV ---
    row_max_k<<<Bd*Hd*Sd, 128>>>(qk, rowmax);
    attn_pv<<<dim3(1, Sd/128, Bd*Hd), 256>>>(qk, v, rowmax, wv, rowsum);
    norm_wv<<<Md, 256>>>(wv, rowsum);

    // --- o projection: base + LoRA, into d_out[0 : B*S*D] ---
    sgemm_nt<<<dim3(8,32,1),256>>>(wv, oW, out, Md, Dd, Dd, Dd, Dd, Dd,
                                   0,0,0,0,0,0,1, 1.f, ob, nullptr, 0);
    tr_loraB<<<(Dd*64+255)/256, 256>>>(oB, Bt);
    sgemm_nt<<<dim3(1,32,1),256>>>(wv, oA, h, Md, 64, Dd, Dd, Dd, 64,
                                   0,0,0,0,0,0,1, 1.f, nullptr, route, 0);
    sgemm_nt<<<dim3(8,32,1),256>>>(h, Bt, out, Md, Dd, 64, 64, 64, Dd,
                                   0,0,0,0,0,0,1, 2.0f, nullptr, nullptr, 1);
}